// round 17
// baseline (speedup 1.0000x reference)
#include <cuda_runtime.h>
#include <cuda_fp16.h>
#include <cstdint>

// R17: warp-pair n-split. Pair (2w,2w+1) shares 16 voxels; each warp reads only
// its n-half of the weight tables (crossbar -30%) and halves are exchanged via
// SMEM with named pair barriers. 3 CTAs/SM, GRID=456, sigmoid gelu.

#define SP     262144
#define TB     256
#define GRID   456
#define NTILES 8192      // 524288 voxels / 64 per CTA-tile (4 pairs x 16)

// smem byte offsets
#define O_W2T  0         // 2048 * 16
#define O_W3T  32768     // 1024 * 16
#define O_W1T  49152     // 256 * 8
#define O_B1H  51200     // 64 * 4
#define O_B2H  51456
#define O_B3H  51712     // 32 * 4
#define O_W4H  51840     // 96 * 4
#define O_B4   52224     // 3 f32 + pad
#define O_XB   52240     // 4 pairs * 4096 = 16384 activation exchange
#define O_PB   68624     // 8 warp-slots * 192 = 1536 (pad 2048) pe exchange
#define O_LZ   70672     // 2 * 64 * 12 = 1536 (tile-parity double buffer)
#define SMEM_BYTES 72208

#define MMAH16(c0, c1, a0, a1, a2, a3, b0, b1) asm volatile( \
    "mma.sync.aligned.m16n8k16.row.col.f16.f16.f16.f16 " \
    "{%0,%1}, {%2,%3,%4,%5}, {%6,%7}, {%0,%1};" \
    : "+r"(c0), "+r"(c1) \
    : "r"(a0), "r"(a1), "r"(a2), "r"(a3), "r"(b0), "r"(b1))

#define MMAH8(c0, c1, a0, a1, b0) asm volatile( \
    "mma.sync.aligned.m16n8k8.row.col.f16.f16.f16.f16 " \
    "{%0,%1}, {%2,%3}, {%4}, {%0,%1};" \
    : "+r"(c0), "+r"(c1) : "r"(a0), "r"(a1), "r"(b0))

#define BARP() asm volatile("bar.sync %0, 64;" :: "r"(pair + 1) : "memory")

__device__ __forceinline__ uint32_t smem_u32(const void* p) {
    uint32_t a;
    asm("{ .reg .u64 t; cvta.to.shared.u64 t, %1; cvt.u32.u64 %0, t; }" : "=r"(a) : "l"(p));
    return a;
}
__device__ __forceinline__ uint32_t lds32(uint32_t a) {
    uint32_t v; asm volatile("ld.shared.b32 %0, [%1];" : "=r"(v) : "r"(a)); return v;
}
__device__ __forceinline__ uint2 lds64(uint32_t a) {
    uint2 v; asm volatile("ld.shared.v2.b32 {%0,%1}, [%2];" : "=r"(v.x), "=r"(v.y) : "r"(a)); return v;
}
__device__ __forceinline__ uint4 lds128(uint32_t a) {
    uint4 v;
    asm volatile("ld.shared.v4.b32 {%0,%1,%2,%3}, [%4];"
                 : "=r"(v.x), "=r"(v.y), "=r"(v.z), "=r"(v.w) : "r"(a));
    return v;
}
__device__ __forceinline__ void sts64(uint32_t a, uint32_t x, uint32_t y) {
    asm volatile("st.shared.v2.b32 [%0], {%1,%2};" :: "r"(a), "r"(x), "r"(y) : "memory");
}
__device__ __forceinline__ void sts32(uint32_t a, uint32_t x) {
    asm volatile("st.shared.b32 [%0], %1;" :: "r"(a), "r"(x) : "memory");
}
__device__ __forceinline__ uint32_t packh(float a, float b) {
    __half2 h = __floats2half2_rn(a, b);
    return *(uint32_t*)&h;
}
// bias-add + gelu (sigmoid form): 0.5x(1+tanh(0.851x))
__device__ __forceinline__ uint32_t gb(uint32_t cu, uint32_t bu) {
    __half2 x = __hadd2(*(__half2*)&cu, *(__half2*)&bu);
    __half2 z = __hmul2(x, __float2half2_rn(0.851f));
    uint32_t zi = *(uint32_t*)&z, ti;
    asm("tanh.approx.f16x2 %0, %1;" : "=r"(ti) : "r"(zi));
    __half2 t = *(__half2*)&ti;
    __half2 hh = __hmul2(x, __float2half2_rn(0.5f));
    __half2 g = __hfma2(hh, t, hh);
    return *(uint32_t*)&g;
}

__global__ void __launch_bounds__(TB, 3)
mhd_ns(const float* __restrict__ flow, const float* __restrict__ Bf,
       const float* __restrict__ W1, const float* __restrict__ b1,
       const float* __restrict__ W2, const float* __restrict__ b2,
       const float* __restrict__ W3, const float* __restrict__ b3,
       const float* __restrict__ W4, const float* __restrict__ b4,
       float* __restrict__ out)
{
    extern __shared__ char smc[];
    const int tid  = threadIdx.x;
    const int wid  = tid >> 5;
    const int lane = tid & 31;
    const int q    = lane & 3;
    const int rsub = lane >> 2;
    const int pair = wid >> 1;      // 0..3
    const int wn   = wid & 1;       // n-half
    const uint32_t smb = smem_u32(smc);

    // ---------------- stage weight B-fragment tables (unchanged layout) ----------
    for (int e = tid; e < 2048; e += TB) {      // W2T
        int l = e & 31, tp = (e >> 5) & 7, sx = e >> 8;
        int n0 = (2 * tp) * 8 + (l >> 2), n1 = n0 + 8;
        int k0 = sx * 16 + (l & 3) * 2;
        uint4 v;
        v.x = packh(W2[k0 * 128 + n0],       W2[(k0 + 1) * 128 + n0]);
        v.y = packh(W2[(k0 + 8) * 128 + n0], W2[(k0 + 9) * 128 + n0]);
        v.z = packh(W2[k0 * 128 + n1],       W2[(k0 + 1) * 128 + n1]);
        v.w = packh(W2[(k0 + 8) * 128 + n1], W2[(k0 + 9) * 128 + n1]);
        *(uint4*)(smc + O_W2T + e * 16) = v;
    }
    for (int e = tid; e < 1024; e += TB) {      // W3T
        int l = e & 31, tp = (e >> 5) & 3, sx = e >> 7;
        int n0 = (2 * tp) * 8 + (l >> 2), n1 = n0 + 8;
        int k0 = sx * 16 + (l & 3) * 2;
        uint4 v;
        v.x = packh(W3[k0 * 64 + n0],       W3[(k0 + 1) * 64 + n0]);
        v.y = packh(W3[(k0 + 8) * 64 + n0], W3[(k0 + 9) * 64 + n0]);
        v.z = packh(W3[k0 * 64 + n1],       W3[(k0 + 1) * 64 + n1]);
        v.w = packh(W3[(k0 + 8) * 64 + n1], W3[(k0 + 9) * 64 + n1]);
        *(uint4*)(smc + O_W3T + e * 16) = v;
    }
    for (int e = tid; e < 256; e += TB) {       // W1T (k>=6 zero)
        int l = e & 31, tp = e >> 5;
        int n0 = (2 * tp) * 8 + (l >> 2), n1 = n0 + 8;
        int k0 = (l & 3) * 2;
        float a0 = (k0 < 6) ? W1[k0 * 128 + n0] : 0.f;
        float a1 = (k0 + 1 < 6) ? W1[(k0 + 1) * 128 + n0] : 0.f;
        float a2 = (k0 < 6) ? W1[k0 * 128 + n1] : 0.f;
        float a3 = (k0 + 1 < 6) ? W1[(k0 + 1) * 128 + n1] : 0.f;
        uint2 v; v.x = packh(a0, a1); v.y = packh(a2, a3);
        *(uint2*)(smc + O_W1T + e * 8) = v;
    }
    for (int i = tid; i < 64; i += TB)
        *(uint32_t*)(smc + O_B1H + i * 4) = packh(b1[(i >> 2) * 8 + (i & 3) * 2],
                                                  b1[(i >> 2) * 8 + (i & 3) * 2 + 1]);
    for (int i = tid; i < 64; i += TB)
        *(uint32_t*)(smc + O_B2H + i * 4) = packh(b2[(i >> 2) * 8 + (i & 3) * 2],
                                                  b2[(i >> 2) * 8 + (i & 3) * 2 + 1]);
    for (int i = tid; i < 32; i += TB)
        *(uint32_t*)(smc + O_B3H + i * 4) = packh(b3[(i >> 2) * 8 + (i & 3) * 2],
                                                  b3[(i >> 2) * 8 + (i & 3) * 2 + 1]);
    for (int i = tid; i < 96; i += TB) {
        int c = i >> 5, p = i & 31;
        *(uint32_t*)(smc + O_W4H + i * 4) = packh(W4[2 * p * 3 + c], W4[(2 * p + 1) * 3 + c]);
    }
    if (tid < 3) ((float*)(smc + O_B4))[tid] = b4[tid];
    __syncthreads();

    const uint32_t xb = smb + O_XB + (uint32_t)pair * 4096;

    for (int tile = blockIdx.x; tile < NTILES; tile += GRID) {
        const int vbase = tile * 64 + pair * 16;
        const int b  = vbase >> 18;
        const int sb = vbase & (SP - 1);
        const float* Fb = flow + b * 3 * SP;
        const float* Bx = Bf + b * 3 * SP;
        const float* By = Bx + SP;
        const float* Bz = Bx + 2 * SP;
        const uint32_t lzo = O_LZ + (uint32_t)(tile & 1) * 768;

        // ---------------- P0: features (both warps); lorentz (odd warp) --------
        const int s0 = sb + rsub, s1 = s0 + 8;
        uint32_t fa0, fa1;
        {
            float l0, h0, l1, h1;
            if (q == 0)      { l0 = Fb[s0]; h0 = Fb[SP + s0]; l1 = Fb[s1]; h1 = Fb[SP + s1]; }
            else if (q == 1) { l0 = Fb[2 * SP + s0]; h0 = Bx[s0]; l1 = Fb[2 * SP + s1]; h1 = Bx[s1]; }
            else if (q == 2) { l0 = By[s0]; h0 = Bz[s0]; l1 = By[s1]; h1 = Bz[s1]; }
            else             { l0 = h0 = l1 = h1 = 0.f; }
            fa0 = packh(l0, h0);
            fa1 = packh(l1, h1);
        }
        if (wn && lane < 16) {
            const int sm = sb + lane;
            const int h = sm >> 12, w = (sm >> 6) & 63, d = sm & 63;
            const int H = h << 12, Wo = w << 6;
            const int hp = ((h + 1) & 63) << 12, hm = ((h - 1) & 63) << 12;
            const int wp = ((w + 1) & 63) << 6,  wm2 = ((w - 1) & 63) << 6;
            const int dp = (d + 1) & 63, dm = (d - 1) & 63;
            const float bx = Bx[H + Wo + d], by = By[H + Wo + d], bz = Bz[H + Wo + d];
            const float Jx = 0.5f * ((Bz[H + wp + d] - Bz[H + wm2 + d]) - (By[H + Wo + dp] - By[H + Wo + dm]));
            const float Jy = 0.5f * ((Bx[H + Wo + dp] - Bx[H + Wo + dm]) - (Bz[hp + Wo + d] - Bz[hm + Wo + d]));
            const float Jz = 0.5f * ((By[hp + Wo + d] - By[hm + Wo + d]) - (Bx[H + wp + d] - Bx[H + wm2 + d]));
            float* lz = (float*)(smc + lzo) + (pair * 16 + lane) * 3;
            lz[0] = (Jy * bz - Jz * by) * 2500.0f;
            lz[1] = (Jz * bx - Jx * bz) * 2500.0f;
            lz[2] = (Jx * by - Jy * bx) * 2500.0f;
        }

        uint32_t myA[8][2];

        // ---------------- L1 (my n-half): 4 lds64, 8 MMAH8 ----------------
        {
            uint32_t c1[8][2];
            #pragma unroll
            for (int t = 0; t < 8; t++) { c1[t][0] = 0u; c1[t][1] = 0u; }
            #pragma unroll
            for (int tpl = 0; tpl < 4; tpl++) {
                uint2 B1f = lds64(smb + O_W1T + (uint32_t)((wn * 4 + tpl) * 32 + lane) * 8);
                MMAH8(c1[2 * tpl][0], c1[2 * tpl][1], fa0, fa1, B1f.x);
                MMAH8(c1[2 * tpl + 1][0], c1[2 * tpl + 1][1], fa0, fa1, B1f.y);
            }
            #pragma unroll
            for (int tl = 0; tl < 8; tl++) {
                uint32_t bb = lds32(smb + O_B1H + (uint32_t)(((wn * 8 + tl) * 4 + q)) * 4);
                myA[tl][0] = gb(c1[tl][0], bb);
                myA[tl][1] = gb(c1[tl][1], bb);
            }
        }

        uint32_t aLo[8][2], aHi[8][2];
        // ---------------- exchange 1 (store, bar, load, bar) ----------------
        if (wn == 0) {
            #pragma unroll
            for (int tl = 0; tl < 8; tl++) sts64(xb + (uint32_t)(tl * 32 + lane) * 8, myA[tl][0], myA[tl][1]);
            BARP();
            #pragma unroll
            for (int tl = 0; tl < 8; tl++) { uint2 v = lds64(xb + (uint32_t)((8 + tl) * 32 + lane) * 8); aHi[tl][0] = v.x; aHi[tl][1] = v.y; }
            #pragma unroll
            for (int tl = 0; tl < 8; tl++) { aLo[tl][0] = myA[tl][0]; aLo[tl][1] = myA[tl][1]; }
            BARP();
        } else {
            #pragma unroll
            for (int tl = 0; tl < 8; tl++) sts64(xb + (uint32_t)((8 + tl) * 32 + lane) * 8, myA[tl][0], myA[tl][1]);
            BARP();
            #pragma unroll
            for (int tl = 0; tl < 8; tl++) { uint2 v = lds64(xb + (uint32_t)(tl * 32 + lane) * 8); aLo[tl][0] = v.x; aLo[tl][1] = v.y; }
            #pragma unroll
            for (int tl = 0; tl < 8; tl++) { aHi[tl][0] = myA[tl][0]; aHi[tl][1] = myA[tl][1]; }
            BARP();
        }

        // ---------------- L2 (my n-half): 32 lds128, 64 MMAH16 ----------------
        {
            uint32_t c2[8][2];
            #pragma unroll
            for (int t = 0; t < 8; t++) { c2[t][0] = 0u; c2[t][1] = 0u; }
            #pragma unroll
            for (int sx = 0; sx < 4; sx++) {
                #pragma unroll
                for (int tpl = 0; tpl < 4; tpl++) {
                    uint4 Bw = lds128(smb + O_W2T + (uint32_t)((sx * 8 + wn * 4 + tpl) * 32 + lane) * 16);
                    MMAH16(c2[2 * tpl][0], c2[2 * tpl][1],
                           aLo[2 * sx][0], aLo[2 * sx][1], aLo[2 * sx + 1][0], aLo[2 * sx + 1][1], Bw.x, Bw.y);
                    MMAH16(c2[2 * tpl + 1][0], c2[2 * tpl + 1][1],
                           aLo[2 * sx][0], aLo[2 * sx][1], aLo[2 * sx + 1][0], aLo[2 * sx + 1][1], Bw.z, Bw.w);
                }
            }
            #pragma unroll
            for (int sx = 4; sx < 8; sx++) {
                const int sl = sx - 4;
                #pragma unroll
                for (int tpl = 0; tpl < 4; tpl++) {
                    uint4 Bw = lds128(smb + O_W2T + (uint32_t)((sx * 8 + wn * 4 + tpl) * 32 + lane) * 16);
                    MMAH16(c2[2 * tpl][0], c2[2 * tpl][1],
                           aHi[2 * sl][0], aHi[2 * sl][1], aHi[2 * sl + 1][0], aHi[2 * sl + 1][1], Bw.x, Bw.y);
                    MMAH16(c2[2 * tpl + 1][0], c2[2 * tpl + 1][1],
                           aHi[2 * sl][0], aHi[2 * sl][1], aHi[2 * sl + 1][0], aHi[2 * sl + 1][1], Bw.z, Bw.w);
                }
            }
            #pragma unroll
            for (int tl = 0; tl < 8; tl++) {
                uint32_t bb = lds32(smb + O_B2H + (uint32_t)(((wn * 8 + tl) * 4 + q)) * 4);
                myA[tl][0] = gb(c2[tl][0], bb);
                myA[tl][1] = gb(c2[tl][1], bb);
            }
        }

        // ---------------- exchange 2 (store, bar, load; bar4 later covers) -----
        if (wn == 0) {
            #pragma unroll
            for (int tl = 0; tl < 8; tl++) sts64(xb + (uint32_t)(tl * 32 + lane) * 8, myA[tl][0], myA[tl][1]);
            BARP();
            #pragma unroll
            for (int tl = 0; tl < 8; tl++) { uint2 v = lds64(xb + (uint32_t)((8 + tl) * 32 + lane) * 8); aHi[tl][0] = v.x; aHi[tl][1] = v.y; }
            #pragma unroll
            for (int tl = 0; tl < 8; tl++) { aLo[tl][0] = myA[tl][0]; aLo[tl][1] = myA[tl][1]; }
        } else {
            #pragma unroll
            for (int tl = 0; tl < 8; tl++) sts64(xb + (uint32_t)((8 + tl) * 32 + lane) * 8, myA[tl][0], myA[tl][1]);
            BARP();
            #pragma unroll
            for (int tl = 0; tl < 8; tl++) { uint2 v = lds64(xb + (uint32_t)(tl * 32 + lane) * 8); aLo[tl][0] = v.x; aLo[tl][1] = v.y; }
            #pragma unroll
            for (int tl = 0; tl < 8; tl++) { aHi[tl][0] = myA[tl][0]; aHi[tl][1] = myA[tl][1]; }
        }

        // ---------------- L3 (my n-half): 16 lds128, 32 MMAH16 ----------------
        uint32_t c3[4][2];
        #pragma unroll
        for (int t = 0; t < 4; t++) { c3[t][0] = 0u; c3[t][1] = 0u; }
        #pragma unroll
        for (int sx = 0; sx < 4; sx++) {
            #pragma unroll
            for (int tpl = 0; tpl < 2; tpl++) {
                uint4 Bw = lds128(smb + O_W3T + (uint32_t)((sx * 4 + wn * 2 + tpl) * 32 + lane) * 16);
                MMAH16(c3[2 * tpl][0], c3[2 * tpl][1],
                       aLo[2 * sx][0], aLo[2 * sx][1], aLo[2 * sx + 1][0], aLo[2 * sx + 1][1], Bw.x, Bw.y);
                MMAH16(c3[2 * tpl + 1][0], c3[2 * tpl + 1][1],
                       aLo[2 * sx][0], aLo[2 * sx][1], aLo[2 * sx + 1][0], aLo[2 * sx + 1][1], Bw.z, Bw.w);
            }
        }
        #pragma unroll
        for (int sx = 4; sx < 8; sx++) {
            const int sl = sx - 4;
            #pragma unroll
            for (int tpl = 0; tpl < 2; tpl++) {
                uint4 Bw = lds128(smb + O_W3T + (uint32_t)((sx * 4 + wn * 2 + tpl) * 32 + lane) * 16);
                MMAH16(c3[2 * tpl][0], c3[2 * tpl][1],
                       aHi[2 * sl][0], aHi[2 * sl][1], aHi[2 * sl + 1][0], aHi[2 * sl + 1][1], Bw.x, Bw.y);
                MMAH16(c3[2 * tpl + 1][0], c3[2 * tpl + 1][1],
                       aHi[2 * sl][0], aHi[2 * sl][1], aHi[2 * sl + 1][0], aHi[2 * sl + 1][1], Bw.z, Bw.w);
            }
        }
        #pragma unroll
        for (int tl = 0; tl < 4; tl++) {
            uint32_t bb = lds32(smb + O_B3H + (uint32_t)(((wn * 4 + tl) * 4 + q)) * 4);
            c3[tl][0] = gb(c3[tl][0], bb);
            c3[tl][1] = gb(c3[tl][1], bb);
        }

        // ---------------- L4 partial over my 32 feats + pair reduce ------------
        __half2 acc[2][3];
        #pragma unroll
        for (int r = 0; r < 2; r++)
            #pragma unroll
            for (int cc = 0; cc < 3; cc++) acc[r][cc] = __float2half2_rn(0.f);
        #pragma unroll
        for (int tl = 0; tl < 4; tl++) {
            #pragma unroll
            for (int cc = 0; cc < 3; cc++) {
                uint32_t wu = lds32(smb + O_W4H + (uint32_t)((cc * 32 + (wn * 4 + tl) * 4 + q)) * 4);
                __half2 wh = *(__half2*)&wu;
                acc[0][cc] = __hfma2(*(__half2*)&c3[tl][0], wh, acc[0][cc]);
                acc[1][cc] = __hfma2(*(__half2*)&c3[tl][1], wh, acc[1][cc]);
            }
        }
        float pp[2][3];
        #pragma unroll
        for (int r = 0; r < 2; r++)
            #pragma unroll
            for (int cc = 0; cc < 3; cc++) {
                float2 f = __half22float2(acc[r][cc]);
                float vv = f.x + f.y;
                vv += __shfl_xor_sync(0xffffffffu, vv, 1);
                vv += __shfl_xor_sync(0xffffffffu, vv, 2);
                pp[r][cc] = vv;
            }
        const uint32_t pbme = smb + O_PB + (uint32_t)(pair * 2 + wn) * 192 + (uint32_t)rsub * 24;
        if (q == 0) {
            #pragma unroll
            for (int r = 0; r < 2; r++)
                #pragma unroll
                for (int cc = 0; cc < 3; cc++)
                    sts32(pbme + (r * 3 + cc) * 4, __float_as_uint(pp[r][cc]));
        }
        BARP();
        const uint32_t pbot = smb + O_PB + (uint32_t)(pair * 2 + 1 - wn) * 192 + (uint32_t)rsub * 24;
        float pe[2][3];
        #pragma unroll
        for (int r = 0; r < 2; r++)
            #pragma unroll
            for (int cc = 0; cc < 3; cc++)
                pe[r][cc] = pp[r][cc] + __uint_as_float(lds32(pbot + (r * 3 + cc) * 4))
                          + ((const float*)(smc + O_B4))[cc];

        // ---------------- store: warp wn stores its row-half -------------------
        if (q < 3) {
            float* ob = out + b * 3 * SP + q * SP;
            if (wn == 0) {
                const float L0 = ((const float*)(smc + lzo))[(pair * 16 + rsub) * 3 + q];
                ob[s0] = L0 + 0.1f * pe[0][q];
            } else {
                const float L1 = ((const float*)(smc + lzo))[(pair * 16 + rsub + 8) * 3 + q];
                ob[s1] = L1 + 0.1f * pe[1][q];
            }
        }
    }
}

extern "C" void kernel_launch(void* const* d_in, const int* in_sizes, int n_in,
                              void* d_out, int out_size)
{
    (void)in_sizes; (void)n_in; (void)out_size;
    cudaFuncSetAttribute(mhd_ns, cudaFuncAttributeMaxDynamicSharedMemorySize, SMEM_BYTES);
    mhd_ns<<<GRID, TB, SMEM_BYTES>>>(
        (const float*)d_in[0], (const float*)d_in[1], (const float*)d_in[2],
        (const float*)d_in[3], (const float*)d_in[4], (const float*)d_in[5],
        (const float*)d_in[6], (const float*)d_in[7], (const float*)d_in[8],
        (const float*)d_in[9], (float*)d_out);
}